// round 6
// baseline (speedup 1.0000x reference)
#include <cuda_runtime.h>
#include <cuda_bf16.h>
#include <math_constants.h>
#include <cstdint>

#define H 128
#define NPAD 1048576
#define SEG_CAP 65536

// B half tile: 128 k-rows x 72 bf16 stride (144 B)
#define RSTRIDE_B 144
#define B_BYTES (128 * RSTRIDE_B)        // 18432

#define OFF_B_HI  0
#define OFF_B_LO  18432
#define OFF_SGATE 36864                  // 4 x 64 floats = 1024 B
#define OFF_SB1   37888                  // 256 B
#define OFF_SW2   38144                  // 256 B
#define SMEM_TOTAL 38400

__device__ float d_gate2[2 * NPAD];
__device__ int   d_seg_start[SEG_CAP];
__device__ int   d_seg_end[SEG_CAP];
__device__ __nv_bfloat16 d_W1hi[H * H];
__device__ __nv_bfloat16 d_W1lo[H * H];

// ---------------------------------------------------------------------------
__device__ __forceinline__ uint32_t smem_u32(const void* p) {
    uint32_t a;
    asm("{ .reg .u64 t; cvta.to.shared.u64 t, %1; cvt.u32.u64 %0, t; }"
        : "=r"(a) : "l"(p));
    return a;
}
__device__ __forceinline__ void ldsm_x4_t(uint32_t* r, uint32_t addr) {
    asm volatile("ldmatrix.sync.aligned.m8n8.x4.trans.shared.b16 {%0,%1,%2,%3}, [%4];"
                 : "=r"(r[0]), "=r"(r[1]), "=r"(r[2]), "=r"(r[3]) : "r"(addr));
}
__device__ __forceinline__ void mma16816(float* d, const uint32_t* a,
                                         const uint32_t* b) {
    asm volatile(
        "mma.sync.aligned.m16n8k16.row.col.f32.bf16.bf16.f32 "
        "{%0,%1,%2,%3}, {%4,%5,%6,%7}, {%8,%9}, {%0,%1,%2,%3};"
        : "+f"(d[0]), "+f"(d[1]), "+f"(d[2]), "+f"(d[3])
        : "r"(a[0]), "r"(a[1]), "r"(a[2]), "r"(a[3]), "r"(b[0]), "r"(b[1]));
}
__device__ __forceinline__ uint32_t pack_hi(float2 v) {
    __nv_bfloat162 h = __floats2bfloat162_rn(v.x, v.y);
    return *(uint32_t*)&h;
}
__device__ __forceinline__ uint32_t pack_lo(float2 v, uint32_t hiP) {
    __nv_bfloat162 h = *(__nv_bfloat162*)&hiP;
    __nv_bfloat162 l = __floats2bfloat162_rn(v.x - __bfloat162float(h.x),
                                             v.y - __bfloat162float(h.y));
    return *(uint32_t*)&l;
}

// ---------------------------------------------------------------------------
// Segment bounds
// ---------------------------------------------------------------------------
__global__ void init_bounds_kernel(int B) {
    int b = blockIdx.x * blockDim.x + threadIdx.x;
    if (b < B) { d_seg_start[b] = -1; d_seg_end[b] = -1; }
}
__global__ void bounds_kernel(const int* __restrict__ bi, int N) {
    int n = blockIdx.x * blockDim.x + threadIdx.x;
    if (n >= N) return;
    int b = bi[n];
    if (n == 0 || bi[n - 1] != b) d_seg_start[b] = n;
    if (n == N - 1 || bi[n + 1] != b) d_seg_end[b] = n + 1;
}

// ---------------------------------------------------------------------------
// W1 -> bf16 hi/lo split (runs once)
// ---------------------------------------------------------------------------
__global__ void prep_w1_kernel(const float* __restrict__ W1) {
    int idx = blockIdx.x * blockDim.x + threadIdx.x;
    if (idx >= H * H) return;
    float v = W1[idx];
    __nv_bfloat16 hi = __float2bfloat16(v);
    __nv_bfloat16 lo = __float2bfloat16(v - __bfloat162float(hi));
    d_W1hi[idx] = hi;
    d_W1lo[idx] = lo;
}

// ---------------------------------------------------------------------------
// Gate kernel: CTA = (64-row tile, 64-col half). 8 warps (2M x 4N),
// warp tile 32x16, acc 16 regs. A fragments loaded straight from gmem
// (fp32 -> bf16 hi/lo in regs), B (W1 slice) hi/lo in smem.
// NO barriers in the mainloop; 1-step gmem prefetch per warp.
// ---------------------------------------------------------------------------
__global__ __launch_bounds__(256, 3) void gate_mma_kernel(
    const float* __restrict__ x, const float* __restrict__ b1,
    const float* __restrict__ W2, int N)
{
    extern __shared__ char smem[];
    const uint32_t sb = smem_u32(smem);
    const int tid = threadIdx.x;
    const int wid = tid >> 5, lane = tid & 31;
    const int warp_m = wid & 1;          // rows warp_m*32
    const int warp_n = wid >> 1;         // local cols warp_n*16
    const int tile = blockIdx.x >> 1;
    const int half = blockIdx.x & 1;
    const long m0 = (long)tile * 64;

    float* sgate = (float*)(smem + OFF_SGATE);
    float* sb1   = (float*)(smem + OFF_SB1);
    float* sw2   = (float*)(smem + OFF_SW2);
    if (tid < 64) {
        sb1[tid] = b1[half * 64 + tid];
        sw2[tid] = W2[half * 64 + tid];
    }
    // ---- B half slice: bf16 hi/lo gmem -> smem (1024 uint4 each) ----
#pragma unroll
    for (int it = 0; it < 4; it++) {
        int idx = it * 256 + tid;
        int k = idx >> 3;
        int n8 = (idx & 7) << 3;
        uint32_t off = (uint32_t)k * RSTRIDE_B + (uint32_t)n8 * 2;
        *(uint4*)(smem + OFF_B_HI + off) = *(const uint4*)(d_W1hi + k * H + half * 64 + n8);
        *(uint4*)(smem + OFF_B_LO + off) = *(const uint4*)(d_W1lo + k * H + half * 64 + n8);
    }

    // per-lane A row pointers (rows r0 + {0,8,16,24}), clamped for last tile
    const int r0 = warp_m * 32 + (lane >> 2);
    const int c0 = (lane & 3) * 2;
    const float* rp[4];
#pragma unroll
    for (int j = 0; j < 4; j++) {
        long gm = m0 + r0 + j * 8;
        if (gm > N - 1) gm = N - 1;
        rp[j] = x + (size_t)gm * H + c0;
    }

    // prologue prefetch (k=0): pf[mi][{r,r+8} x {c,c+8}]
    float2 pf[2][4];
#pragma unroll
    for (int mi = 0; mi < 2; mi++) {
        pf[mi][0] = *(const float2*)(rp[mi * 2]);
        pf[mi][1] = *(const float2*)(rp[mi * 2 + 1]);
        pf[mi][2] = *(const float2*)(rp[mi * 2] + 8);
        pf[mi][3] = *(const float2*)(rp[mi * 2 + 1] + 8);
    }
    __syncthreads();   // B visible

    float acc[2][2][4];
#pragma unroll
    for (int mi = 0; mi < 2; mi++)
#pragma unroll
        for (int ni = 0; ni < 2; ni++)
#pragma unroll
            for (int r = 0; r < 4; r++) acc[mi][ni][r] = 0.f;

    const uint32_t b_addr_base = sb + (uint32_t)(lane & 15) * RSTRIDE_B
                               + (uint32_t)(warp_n * 16 + (lane >> 4) * 8) * 2;

#pragma unroll
    for (int k = 0; k < 8; k++) {
        // convert prefetched fp32 -> bf16 hi/lo fragments
        uint32_t ah[2][4], al[2][4];
#pragma unroll
        for (int mi = 0; mi < 2; mi++)
#pragma unroll
            for (int p = 0; p < 4; p++) {
                ah[mi][p] = pack_hi(pf[mi][p]);
                al[mi][p] = pack_lo(pf[mi][p], ah[mi][p]);
            }
        // prefetch next k-step
        if (k < 7) {
            const int co = (k + 1) * 16;
#pragma unroll
            for (int mi = 0; mi < 2; mi++) {
                pf[mi][0] = *(const float2*)(rp[mi * 2] + co);
                pf[mi][1] = *(const float2*)(rp[mi * 2 + 1] + co);
                pf[mi][2] = *(const float2*)(rp[mi * 2] + co + 8);
                pf[mi][3] = *(const float2*)(rp[mi * 2 + 1] + co + 8);
            }
        }
        // B fragments (16 cols, hi+lo)
        uint32_t bh[4], bl[4];
        const uint32_t baddr = b_addr_base + (uint32_t)k * 16 * RSTRIDE_B;
        ldsm_x4_t(bh, OFF_B_HI + baddr);
        ldsm_x4_t(bl, OFF_B_LO + baddr);
        // 12 MMAs: hi*hi + lo*hi + hi*lo
#pragma unroll
        for (int mi = 0; mi < 2; mi++) {
            mma16816(acc[mi][0], ah[mi], &bh[0]);
            mma16816(acc[mi][1], ah[mi], &bh[2]);
            mma16816(acc[mi][0], al[mi], &bh[0]);
            mma16816(acc[mi][1], al[mi], &bh[2]);
            mma16816(acc[mi][0], ah[mi], &bl[0]);
            mma16816(acc[mi][1], ah[mi], &bl[2]);
        }
    }

    // ---- epilogue: silu + dot(W2 slice), warp row-reduce ----
    float part[2][2] = {{0.f, 0.f}, {0.f, 0.f}};
#pragma unroll
    for (int mi = 0; mi < 2; mi++)
#pragma unroll
        for (int ni = 0; ni < 2; ni++)
#pragma unroll
            for (int r = 0; r < 4; r++) {
                int col = warp_n * 16 + ni * 8 + (lane & 3) * 2 + (r & 1);
                float vv = acc[mi][ni][r] + sb1[col];
                float sl = vv / (1.f + __expf(-vv));
                part[mi][r >> 1] = fmaf(sl, sw2[col], part[mi][r >> 1]);
            }
#pragma unroll
    for (int mi = 0; mi < 2; mi++)
#pragma unroll
        for (int hh = 0; hh < 2; hh++) {
            float p = part[mi][hh];
            p += __shfl_xor_sync(0xFFFFFFFF, p, 1);
            p += __shfl_xor_sync(0xFFFFFFFF, p, 2);
            part[mi][hh] = p;
        }
    if ((lane & 3) == 0) {
#pragma unroll
        for (int mi = 0; mi < 2; mi++)
#pragma unroll
            for (int hh = 0; hh < 2; hh++) {
                int row = warp_m * 32 + mi * 16 + hh * 8 + (lane >> 2);
                sgate[warp_n * 64 + row] = part[mi][hh];
            }
    }
    __syncthreads();
    if (tid < 64) {
        long gm = m0 + tid;
        if (gm < N)
            d_gate2[(size_t)half * NPAD + gm] =
                sgate[tid] + sgate[64 + tid] + sgate[128 + tid] + sgate[192 + tid];
    }
}

// ---------------------------------------------------------------------------
// Reduce kernel: per-segment mean/max/attention (b2 cancels in softmax)
// ---------------------------------------------------------------------------
__global__ __launch_bounds__(128) void reduce_kernel(
    const float* __restrict__ x, float* __restrict__ out)
{
    int b = blockIdx.x;
    int j = threadIdx.x;
    int s = d_seg_start[b];
    int e = (s < 0) ? 0 : d_seg_end[b];
    if (s < 0) s = 0;

    float sum = 0.f, mx = -CUDART_INF_F;
    float m0 = -CUDART_INF_F, dn0 = 0.f, ac0 = 0.f;
    float m1 = -CUDART_INF_F, dn1 = 0.f, ac1 = 0.f;

    int n = s;
    for (; n + 2 <= e; n += 2) {
        float xv0 = __ldg(x + (size_t)n * H + j);
        float g0  = d_gate2[n] + d_gate2[NPAD + n];
        float xv1 = __ldg(x + (size_t)(n + 1) * H + j);
        float g1  = d_gate2[n + 1] + d_gate2[NPAD + n + 1];
        sum += xv0 + xv1;
        mx = fmaxf(mx, fmaxf(xv0, xv1));
        if (g0 > m0) { float sc = __expf(m0 - g0); dn0 *= sc; ac0 *= sc; m0 = g0; }
        float e0 = __expf(g0 - m0); dn0 += e0; ac0 = fmaf(e0, xv0, ac0);
        if (g1 > m1) { float sc = __expf(m1 - g1); dn1 *= sc; ac1 *= sc; m1 = g1; }
        float e1 = __expf(g1 - m1); dn1 += e1; ac1 = fmaf(e1, xv1, ac1);
    }
    if (n < e) {
        float xv = __ldg(x + (size_t)n * H + j);
        float g  = d_gate2[n] + d_gate2[NPAD + n];
        sum += xv; mx = fmaxf(mx, xv);
        if (g > m0) { float sc = __expf(m0 - g); dn0 *= sc; ac0 *= sc; m0 = g; }
        float ev = __expf(g - m0); dn0 += ev; ac0 = fmaf(ev, xv, ac0);
    }

    int cnt = e - s;
    float denom = 0.f, acc = 0.f;
    if (cnt > 0) {
        float M  = fmaxf(m0, m1);
        float s0 = (m0 > -CUDART_INF_F) ? __expf(m0 - M) : 0.f;
        float s1 = (m1 > -CUDART_INF_F) ? __expf(m1 - M) : 0.f;
        denom = dn0 * s0 + dn1 * s1;
        acc   = ac0 * s0 + ac1 * s1;
    }
    float* o = out + (size_t)b * (3 * H);
    o[j]         = sum / fmaxf((float)cnt, 1.f);
    o[H + j]     = mx;
    o[2 * H + j] = (cnt > 0) ? (acc / denom) : 0.f;
}

// ---------------------------------------------------------------------------
extern "C" void kernel_launch(void* const* d_in, const int* in_sizes, int n_in,
                              void* d_out, int out_size) {
    const float* x  = (const float*)d_in[0];
    const float* W1 = (const float*)d_in[1];
    const float* b1 = (const float*)d_in[2];
    const float* W2 = (const float*)d_in[3];
    const int*   bi = (const int*)d_in[5];

    const int N = in_sizes[5];
    const int B = out_size / (3 * H);
    float* out = (float*)d_out;

    static int inited = 0;
    if (!inited) {
        cudaFuncSetAttribute(gate_mma_kernel,
                             cudaFuncAttributeMaxDynamicSharedMemorySize, SMEM_TOTAL);
        inited = 1;
    }

    const int numTiles = (N + 63) / 64;

    init_bounds_kernel<<<(B + 255) / 256, 256>>>(B);
    bounds_kernel<<<(N + 255) / 256, 256>>>(bi, N);
    prep_w1_kernel<<<(H * H + 255) / 256, 256>>>(W1);
    gate_mma_kernel<<<numTiles * 2, 256, SMEM_TOTAL>>>(x, b1, W2, N);
    reduce_kernel<<<B, H>>>(x, out);
}

// round 7
// speedup vs baseline: 1.4177x; 1.4177x over previous
#include <cuda_runtime.h>
#include <cuda_bf16.h>
#include <math_constants.h>
#include <cstdint>

#define H 128
#define NPAD 1048576
#define SEG_CAP 65536

// strides
#define RST_BF 272                       // bf16 tile row stride (136 elems)
#define RST_32 528                       // fp32 stage row stride (132 floats)

// smem layout (bytes)
#define OFF_B_HI   0                     // 128k x 272 = 34816
#define OFF_B_LO   34816
#define OFF_ABF_HI 69632                 // 64r x 272 = 17408
#define OFF_ABF_LO 87040
#define OFF_A32    104448                // 2 bufs x (64 x 528) = 67584
#define OFF_SGATE  172032                // 4 x 64 floats = 1024
#define OFF_SB1    173056                // 512
#define OFF_SW2    173568                // 512
#define SMEM_TOTAL 174080

__device__ float d_gate[NPAD];
__device__ int   d_seg_start[SEG_CAP];
__device__ int   d_seg_end[SEG_CAP];
__device__ __nv_bfloat16 d_W1hi[H * H];
__device__ __nv_bfloat16 d_W1lo[H * H];

// ---------------------------------------------------------------------------
__device__ __forceinline__ uint32_t smem_u32(const void* p) {
    uint32_t a;
    asm("{ .reg .u64 t; cvta.to.shared.u64 t, %1; cvt.u32.u64 %0, t; }"
        : "=r"(a) : "l"(p));
    return a;
}
__device__ __forceinline__ void ldsm_x4(uint32_t* r, uint32_t addr) {
    asm volatile("ldmatrix.sync.aligned.m8n8.x4.shared.b16 {%0,%1,%2,%3}, [%4];"
                 : "=r"(r[0]), "=r"(r[1]), "=r"(r[2]), "=r"(r[3]) : "r"(addr));
}
__device__ __forceinline__ void ldsm_x4_t(uint32_t* r, uint32_t addr) {
    asm volatile("ldmatrix.sync.aligned.m8n8.x4.trans.shared.b16 {%0,%1,%2,%3}, [%4];"
                 : "=r"(r[0]), "=r"(r[1]), "=r"(r[2]), "=r"(r[3]) : "r"(addr));
}
__device__ __forceinline__ void mma16816(float* d, const uint32_t* a,
                                         const uint32_t* b) {
    asm volatile(
        "mma.sync.aligned.m16n8k16.row.col.f32.bf16.bf16.f32 "
        "{%0,%1,%2,%3}, {%4,%5,%6,%7}, {%8,%9}, {%0,%1,%2,%3};"
        : "+f"(d[0]), "+f"(d[1]), "+f"(d[2]), "+f"(d[3])
        : "r"(a[0]), "r"(a[1]), "r"(a[2]), "r"(a[3]), "r"(b[0]), "r"(b[1]));
}
__device__ __forceinline__ void cp_async16(uint32_t dst, const void* src, int sz) {
    asm volatile("cp.async.cg.shared.global [%0], [%1], 16, %2;"
                 :: "r"(dst), "l"(src), "r"(sz) : "memory");
}
#define CP_COMMIT() asm volatile("cp.async.commit_group;" ::: "memory")
#define CP_WAIT0()  asm volatile("cp.async.wait_group 0;" ::: "memory")

// ---------------------------------------------------------------------------
// Segment bounds
// ---------------------------------------------------------------------------
__global__ void init_bounds_kernel(int B) {
    int b = blockIdx.x * blockDim.x + threadIdx.x;
    if (b < B) { d_seg_start[b] = -1; d_seg_end[b] = -1; }
}
__global__ void bounds_kernel(const int* __restrict__ bi, int N) {
    int n = blockIdx.x * blockDim.x + threadIdx.x;
    if (n >= N) return;
    int b = bi[n];
    if (n == 0 || bi[n - 1] != b) d_seg_start[b] = n;
    if (n == N - 1 || bi[n + 1] != b) d_seg_end[b] = n + 1;
}

// ---------------------------------------------------------------------------
// W1 -> bf16 hi/lo split (runs once)
// ---------------------------------------------------------------------------
__global__ void prep_w1_kernel(const float* __restrict__ W1) {
    int idx = blockIdx.x * blockDim.x + threadIdx.x;
    if (idx >= H * H) return;
    float v = W1[idx];
    __nv_bfloat16 hi = __float2bfloat16(v);
    __nv_bfloat16 lo = __float2bfloat16(v - __bfloat162float(hi));
    d_W1hi[idx] = hi;
    d_W1lo[idx] = lo;
}

// ---------------------------------------------------------------------------
// Persistent gate kernel: 1 CTA/SM, 512 thr (16 warps: 4M x 4N), tile 64x128.
// cp.async double-buffers the raw fp32 x tile; convert fp32->bf16 hi/lo in
// smem; mma.sync bf16 3-product against W1 hi/lo (loaded once per SM).
// ---------------------------------------------------------------------------
__global__ __launch_bounds__(512, 1) void gate_mma_kernel(
    const float* __restrict__ x, const float* __restrict__ b1,
    const float* __restrict__ W2, int N)
{
    extern __shared__ char smem[];
    const uint32_t sb = smem_u32(smem);
    const int tid = threadIdx.x;
    const int wid = tid >> 5, lane = tid & 31;
    const int warp_m = wid & 3;          // rows warp_m*16
    const int warp_n = wid >> 2;         // cols warp_n*32

    float* sgate = (float*)(smem + OFF_SGATE);
    float* sb1   = (float*)(smem + OFF_SB1);
    float* sw2   = (float*)(smem + OFF_SW2);
    if (tid < H) { sb1[tid] = b1[tid]; sw2[tid] = W2[tid]; }

    const int numTiles = (N + 63) / 64;
    const int grid = gridDim.x;

    // ---- issue cp.async for first tile (buf 0) ----
    {
        long m0 = (long)blockIdx.x * 64;
#pragma unroll
        for (int c = 0; c < 4; c++) {
            int chunk = c * 512 + tid;
            int row = chunk >> 5, col16 = chunk & 31;
            long gm = m0 + row;
            uint32_t dst = sb + OFF_A32 + row * RST_32 + col16 * 16;
            const float* src = x + (size_t)(gm < N ? gm : 0) * H + col16 * 4;
            cp_async16(dst, src, gm < N ? 16 : 0);
        }
        CP_COMMIT();
    }

    // ---- B (W1 hi/lo) -> smem once ----
#pragma unroll
    for (int c = 0; c < 4; c++) {
        int chunk = c * 512 + tid;           // 2048 uint4 per matrix
        int k = chunk >> 4, n8 = (chunk & 15) << 3;
        uint32_t off = (uint32_t)k * RST_BF + (uint32_t)n8 * 2;
        *(uint4*)(smem + OFF_B_HI + off) = *(const uint4*)(d_W1hi + k * H + n8);
        *(uint4*)(smem + OFF_B_LO + off) = *(const uint4*)(d_W1lo + k * H + n8);
    }

    // hoisted fragment addresses
    const uint32_t a_off = sb + (uint32_t)(warp_m * 16 + (lane & 15)) * RST_BF
                         + (uint32_t)((lane >> 4) * 8) * 2;
    const uint32_t b_off = sb + (uint32_t)(lane & 15) * RST_BF
                         + (uint32_t)(warp_n * 32 + (lane >> 4) * 8) * 2;

    int buf = 0;
    for (int t = blockIdx.x; t < numTiles; t += grid) {
        const long m0 = (long)t * 64;
        CP_WAIT0();
        __syncthreads();                 // A32[buf] complete + Abf free

        // prefetch next tile into other buffer
        const int tn = t + grid;
        if (tn < numTiles) {
            long m0n = (long)tn * 64;
            uint32_t a32n = sb + OFF_A32 + (buf ^ 1) * 33792;
#pragma unroll
            for (int c = 0; c < 4; c++) {
                int chunk = c * 512 + tid;
                int row = chunk >> 5, col16 = chunk & 31;
                long gm = m0n + row;
                const float* src = x + (size_t)(gm < N ? gm : 0) * H + col16 * 4;
                cp_async16(a32n + row * RST_32 + col16 * 16, src, gm < N ? 16 : 0);
            }
            CP_COMMIT();
        }

        // ---- convert A32[buf] -> Abf hi/lo ----
        {
            const char* a32 = smem + OFF_A32 + buf * 33792;
#pragma unroll
            for (int c = 0; c < 4; c++) {
                int chunk = c * 512 + tid;
                int row = chunk >> 5, col4 = (chunk & 31) << 2;
                float4 v = *(const float4*)(a32 + row * RST_32 + col4 * 4);
                __nv_bfloat16 h0 = __float2bfloat16(v.x), h1 = __float2bfloat16(v.y);
                __nv_bfloat16 h2 = __float2bfloat16(v.z), h3 = __float2bfloat16(v.w);
                __nv_bfloat16 l0 = __float2bfloat16(v.x - __bfloat162float(h0));
                __nv_bfloat16 l1 = __float2bfloat16(v.y - __bfloat162float(h1));
                __nv_bfloat16 l2 = __float2bfloat16(v.z - __bfloat162float(h2));
                __nv_bfloat16 l3 = __float2bfloat16(v.w - __bfloat162float(h3));
                uint32_t off = (uint32_t)row * RST_BF + (uint32_t)col4 * 2;
                uint2 uh, ul;
                uh.x = (uint32_t)__bfloat16_as_ushort(h0) | ((uint32_t)__bfloat16_as_ushort(h1) << 16);
                uh.y = (uint32_t)__bfloat16_as_ushort(h2) | ((uint32_t)__bfloat16_as_ushort(h3) << 16);
                ul.x = (uint32_t)__bfloat16_as_ushort(l0) | ((uint32_t)__bfloat16_as_ushort(l1) << 16);
                ul.y = (uint32_t)__bfloat16_as_ushort(l2) | ((uint32_t)__bfloat16_as_ushort(l3) << 16);
                *(uint2*)(smem + OFF_ABF_HI + off) = uh;
                *(uint2*)(smem + OFF_ABF_LO + off) = ul;
            }
        }
        __syncthreads();                 // Abf visible (also B on first iter)

        // ---- MMA: 3 products ----
        float acc[4][4];
#pragma unroll
        for (int ni = 0; ni < 4; ni++)
#pragma unroll
            for (int r = 0; r < 4; r++) acc[ni][r] = 0.f;

#pragma unroll
        for (int k = 0; k < 8; k++) {
            uint32_t ah[4], al[4];
            ldsm_x4(ah, a_off + (OFF_ABF_HI) + k * 32);
            ldsm_x4(al, a_off + (OFF_ABF_LO) + k * 32);
#pragma unroll
            for (int nb = 0; nb < 2; nb++) {
                uint32_t bh[4], bl[4];
                uint32_t bo = b_off + (uint32_t)k * 16 * RST_BF + nb * 32;
                ldsm_x4_t(bh, bo + OFF_B_HI);
                ldsm_x4_t(bl, bo + OFF_B_LO);
                mma16816(acc[nb * 2],     ah, &bh[0]);
                mma16816(acc[nb * 2 + 1], ah, &bh[2]);
                mma16816(acc[nb * 2],     al, &bh[0]);
                mma16816(acc[nb * 2 + 1], al, &bh[2]);
                mma16816(acc[nb * 2],     ah, &bl[0]);
                mma16816(acc[nb * 2 + 1], ah, &bl[2]);
            }
        }

        // ---- epilogue: silu + dot(W2), warp row-reduce ----
        float part[2] = {0.f, 0.f};
#pragma unroll
        for (int ni = 0; ni < 4; ni++)
#pragma unroll
            for (int r = 0; r < 4; r++) {
                int col = warp_n * 32 + ni * 8 + (lane & 3) * 2 + (r & 1);
                float vv = acc[ni][r] + sb1[col];
                float sl = vv / (1.f + __expf(-vv));
                part[r >> 1] = fmaf(sl, sw2[col], part[r >> 1]);
            }
#pragma unroll
        for (int hh = 0; hh < 2; hh++) {
            float p = part[hh];
            p += __shfl_xor_sync(0xFFFFFFFF, p, 1);
            p += __shfl_xor_sync(0xFFFFFFFF, p, 2);
            part[hh] = p;
        }
        if ((lane & 3) == 0) {
#pragma unroll
            for (int hh = 0; hh < 2; hh++) {
                int row = warp_m * 16 + hh * 8 + (lane >> 2);
                sgate[warp_n * 64 + row] = part[hh];
            }
        }
        __syncthreads();
        if (tid < 64) {
            long gm = m0 + tid;
            if (gm < N)
                d_gate[gm] = sgate[tid] + sgate[64 + tid]
                           + sgate[128 + tid] + sgate[192 + tid];
        }
        buf ^= 1;
    }
}

// ---------------------------------------------------------------------------
// Reduce kernel: per-segment mean/max/attention (b2 cancels in softmax)
// ---------------------------------------------------------------------------
__global__ __launch_bounds__(128) void reduce_kernel(
    const float* __restrict__ x, float* __restrict__ out)
{
    int b = blockIdx.x;
    int j = threadIdx.x;
    int s = d_seg_start[b];
    int e = (s < 0) ? 0 : d_seg_end[b];
    if (s < 0) s = 0;

    float sum = 0.f, mx = -CUDART_INF_F;
    float m0 = -CUDART_INF_F, dn0 = 0.f, ac0 = 0.f;
    float m1 = -CUDART_INF_F, dn1 = 0.f, ac1 = 0.f;

    int n = s;
    for (; n + 2 <= e; n += 2) {
        float xv0 = __ldg(x + (size_t)n * H + j);
        float g0  = d_gate[n];
        float xv1 = __ldg(x + (size_t)(n + 1) * H + j);
        float g1  = d_gate[n + 1];
        sum += xv0 + xv1;
        mx = fmaxf(mx, fmaxf(xv0, xv1));
        if (g0 > m0) { float sc = __expf(m0 - g0); dn0 *= sc; ac0 *= sc; m0 = g0; }
        float e0 = __expf(g0 - m0); dn0 += e0; ac0 = fmaf(e0, xv0, ac0);
        if (g1 > m1) { float sc = __expf(m1 - g1); dn1 *= sc; ac1 *= sc; m1 = g1; }
        float e1 = __expf(g1 - m1); dn1 += e1; ac1 = fmaf(e1, xv1, ac1);
    }
    if (n < e) {
        float xv = __ldg(x + (size_t)n * H + j);
        float g  = d_gate[n];
        sum += xv; mx = fmaxf(mx, xv);
        if (g > m0) { float sc = __expf(m0 - g); dn0 *= sc; ac0 *= sc; m0 = g; }
        float ev = __expf(g - m0); dn0 += ev; ac0 = fmaf(ev, xv, ac0);
    }

    int cnt = e - s;
    float denom = 0.f, acc = 0.f;
    if (cnt > 0) {
        float M  = fmaxf(m0, m1);
        float s0 = (m0 > -CUDART_INF_F) ? __expf(m0 - M) : 0.f;
        float s1 = (m1 > -CUDART_INF_F) ? __expf(m1 - M) : 0.f;
        denom = dn0 * s0 + dn1 * s1;
        acc   = ac0 * s0 + ac1 * s1;
    }
    float* o = out + (size_t)b * (3 * H);
    o[j]         = sum / fmaxf((float)cnt, 1.f);
    o[H + j]     = mx;
    o[2 * H + j] = (cnt > 0) ? (acc / denom) : 0.f;
}

// ---------------------------------------------------------------------------
extern "C" void kernel_launch(void* const* d_in, const int* in_sizes, int n_in,
                              void* d_out, int out_size) {
    const float* x  = (const float*)d_in[0];
    const float* W1 = (const float*)d_in[1];
    const float* b1 = (const float*)d_in[2];
    const float* W2 = (const float*)d_in[3];
    const int*   bi = (const int*)d_in[5];

    const int N = in_sizes[5];
    const int B = out_size / (3 * H);
    float* out = (float*)d_out;

    static int inited = 0;
    static int sms = 148;
    if (!inited) {
        cudaFuncSetAttribute(gate_mma_kernel,
                             cudaFuncAttributeMaxDynamicSharedMemorySize, SMEM_TOTAL);
        int dev = 0;
        cudaGetDevice(&dev);
        cudaDeviceGetAttribute(&sms, cudaDevAttrMultiProcessorCount, dev);
        inited = 1;
    }

    const int numTiles = (N + 63) / 64;
    const int gateGrid = sms < numTiles ? sms : numTiles;

    init_bounds_kernel<<<(B + 255) / 256, 256>>>(B);
    bounds_kernel<<<(N + 255) / 256, 256>>>(bi, N);
    prep_w1_kernel<<<(H * H + 255) / 256, 256>>>(W1);
    gate_mma_kernel<<<gateGrid, 512, SMEM_TOTAL>>>(x, b1, W2, N);
    reduce_kernel<<<B, H>>>(x, out);
}

// round 8
// speedup vs baseline: 1.4392x; 1.0152x over previous
#include <cuda_runtime.h>
#include <cuda_bf16.h>
#include <math_constants.h>
#include <cstdint>

#define H 128
#define NPAD 1048576
#define SEG_CAP 65536

// strides
#define RST_BF 272                       // bf16 tile row stride bytes (136 elems)
#define RST_32 528                       // fp32 stage row stride bytes (132 floats)

// sizes
#define ABF_BUF 34816                    // hi 17408 + lo 17408
#define A32_BUF 33792                    // 64 x 528

// smem layout (bytes)
#define OFF_B_HI   0                     // 128 x 272 = 34816
#define OFF_B_LO   34816
#define OFF_ABF    69632                 // 2 bufs x 34816
#define OFF_A32    139264                // 2 bufs x 33792
#define OFF_SGATE  206848                // 2 bufs x 1024
#define OFF_SB1    208896                // 512
#define OFF_SW2    209408                // 512
#define SMEM_TOTAL 209920

__device__ float d_gate[NPAD];
__device__ int   d_seg_start[SEG_CAP];
__device__ int   d_seg_end[SEG_CAP];
__device__ __nv_bfloat16 d_W1hi[H * H];
__device__ __nv_bfloat16 d_W1lo[H * H];

// ---------------------------------------------------------------------------
__device__ __forceinline__ uint32_t smem_u32(const void* p) {
    uint32_t a;
    asm("{ .reg .u64 t; cvta.to.shared.u64 t, %1; cvt.u32.u64 %0, t; }"
        : "=r"(a) : "l"(p));
    return a;
}
__device__ __forceinline__ void ldsm_x4(uint32_t* r, uint32_t addr) {
    asm volatile("ldmatrix.sync.aligned.m8n8.x4.shared.b16 {%0,%1,%2,%3}, [%4];"
                 : "=r"(r[0]), "=r"(r[1]), "=r"(r[2]), "=r"(r[3]) : "r"(addr));
}
__device__ __forceinline__ void ldsm_x4_t(uint32_t* r, uint32_t addr) {
    asm volatile("ldmatrix.sync.aligned.m8n8.x4.trans.shared.b16 {%0,%1,%2,%3}, [%4];"
                 : "=r"(r[0]), "=r"(r[1]), "=r"(r[2]), "=r"(r[3]) : "r"(addr));
}
__device__ __forceinline__ void mma16816(float* d, const uint32_t* a,
                                         const uint32_t* b) {
    asm volatile(
        "mma.sync.aligned.m16n8k16.row.col.f32.bf16.bf16.f32 "
        "{%0,%1,%2,%3}, {%4,%5,%6,%7}, {%8,%9}, {%0,%1,%2,%3};"
        : "+f"(d[0]), "+f"(d[1]), "+f"(d[2]), "+f"(d[3])
        : "r"(a[0]), "r"(a[1]), "r"(a[2]), "r"(a[3]), "r"(b[0]), "r"(b[1]));
}
__device__ __forceinline__ void cp_async16(uint32_t dst, const void* src, int sz) {
    asm volatile("cp.async.cg.shared.global [%0], [%1], 16, %2;"
                 :: "r"(dst), "l"(src), "r"(sz) : "memory");
}
#define CP_COMMIT() asm volatile("cp.async.commit_group;" ::: "memory")
#define CP_WAIT0()  asm volatile("cp.async.wait_group 0;" ::: "memory")
#define CP_WAIT1()  asm volatile("cp.async.wait_group 1;" ::: "memory")

// ---------------------------------------------------------------------------
// Segment bounds
// ---------------------------------------------------------------------------
__global__ void init_bounds_kernel(int B) {
    int b = blockIdx.x * blockDim.x + threadIdx.x;
    if (b < B) { d_seg_start[b] = -1; d_seg_end[b] = -1; }
}
__global__ void bounds_kernel(const int* __restrict__ bi, int N) {
    int n = blockIdx.x * blockDim.x + threadIdx.x;
    if (n >= N) return;
    int b = bi[n];
    if (n == 0 || bi[n - 1] != b) d_seg_start[b] = n;
    if (n == N - 1 || bi[n + 1] != b) d_seg_end[b] = n + 1;
}

// ---------------------------------------------------------------------------
// W1 -> bf16 hi/lo split (runs once)
// ---------------------------------------------------------------------------
__global__ void prep_w1_kernel(const float* __restrict__ W1) {
    int idx = blockIdx.x * blockDim.x + threadIdx.x;
    if (idx >= H * H) return;
    float v = W1[idx];
    __nv_bfloat16 hi = __float2bfloat16(v);
    __nv_bfloat16 lo = __float2bfloat16(v - __bfloat162float(hi));
    d_W1hi[idx] = hi;
    d_W1lo[idx] = lo;
}

// ---------------------------------------------------------------------------
// fp32 stage buffer -> bf16 hi/lo tile (all 512 threads)
// ---------------------------------------------------------------------------
__device__ __forceinline__ void convert_tile(char* smem, int a32buf, int abfbuf,
                                             int tid) {
    const char* a32 = smem + OFF_A32 + a32buf * A32_BUF;
    char* abf = smem + OFF_ABF + abfbuf * ABF_BUF;
#pragma unroll
    for (int c = 0; c < 4; c++) {
        int chunk = c * 512 + tid;
        int row = chunk >> 5, col4 = (chunk & 31) << 2;
        float4 v = *(const float4*)(a32 + row * RST_32 + col4 * 4);
        __nv_bfloat16 h0 = __float2bfloat16(v.x), h1 = __float2bfloat16(v.y);
        __nv_bfloat16 h2 = __float2bfloat16(v.z), h3 = __float2bfloat16(v.w);
        __nv_bfloat16 l0 = __float2bfloat16(v.x - __bfloat162float(h0));
        __nv_bfloat16 l1 = __float2bfloat16(v.y - __bfloat162float(h1));
        __nv_bfloat16 l2 = __float2bfloat16(v.z - __bfloat162float(h2));
        __nv_bfloat16 l3 = __float2bfloat16(v.w - __bfloat162float(h3));
        uint32_t off = (uint32_t)row * RST_BF + (uint32_t)col4 * 2;
        uint2 uh, ul;
        uh.x = (uint32_t)__bfloat16_as_ushort(h0) | ((uint32_t)__bfloat16_as_ushort(h1) << 16);
        uh.y = (uint32_t)__bfloat16_as_ushort(h2) | ((uint32_t)__bfloat16_as_ushort(h3) << 16);
        ul.x = (uint32_t)__bfloat16_as_ushort(l0) | ((uint32_t)__bfloat16_as_ushort(l1) << 16);
        ul.y = (uint32_t)__bfloat16_as_ushort(l2) | ((uint32_t)__bfloat16_as_ushort(l3) << 16);
        *(uint2*)(abf + off) = uh;
        *(uint2*)(abf + 17408 + off) = ul;
    }
}

__device__ __forceinline__ void issue_cp(const float* __restrict__ x, uint32_t sb,
                                         long t, int a32buf, int N, int tid) {
    long m0 = t * 64;
    uint32_t dst0 = sb + OFF_A32 + a32buf * A32_BUF;
#pragma unroll
    for (int c = 0; c < 4; c++) {
        int chunk = c * 512 + tid;
        int row = chunk >> 5, col16 = chunk & 31;
        long gm = m0 + row;
        const float* src = x + (size_t)(gm < N ? gm : 0) * H + col16 * 4;
        cp_async16(dst0 + row * RST_32 + col16 * 16, src, gm < N ? 16 : 0);
    }
    CP_COMMIT();
}

// ---------------------------------------------------------------------------
// Persistent gate kernel: 1 CTA/SM, 512 thr (16 warps: 4M x 4N), tile 64x128.
// Pipelined: each iteration converts tile t+1 while MMA-ing tile t; warps
// drift inside the phase so LSU/ALU convert overlaps tensor work.
// ---------------------------------------------------------------------------
__global__ __launch_bounds__(512, 1) void gate_mma_kernel(
    const float* __restrict__ x, const float* __restrict__ b1,
    const float* __restrict__ W2, int N)
{
    extern __shared__ char smem[];
    const uint32_t sb = smem_u32(smem);
    const int tid = threadIdx.x;
    const int wid = tid >> 5, lane = tid & 31;
    const int warp_m = wid & 3;          // rows warp_m*16
    const int warp_n = wid >> 2;         // cols warp_n*32

    float* sb1 = (float*)(smem + OFF_SB1);
    float* sw2 = (float*)(smem + OFF_SW2);
    if (tid < H) { sb1[tid] = b1[tid]; sw2[tid] = W2[tid]; }

    const int numTiles = (N + 63) / 64;
    const int grid = gridDim.x;

    // prologue: tile t0 -> A32[0]
    issue_cp(x, sb, blockIdx.x, 0, N, tid);

    // B (W1 hi/lo) -> smem once
#pragma unroll
    for (int c = 0; c < 4; c++) {
        int chunk = c * 512 + tid;           // 2048 uint4 per matrix
        int k = chunk >> 4, n8 = (chunk & 15) << 3;
        uint32_t off = (uint32_t)k * RST_BF + (uint32_t)n8 * 2;
        *(uint4*)(smem + OFF_B_HI + off) = *(const uint4*)(d_W1hi + k * H + n8);
        *(uint4*)(smem + OFF_B_LO + off) = *(const uint4*)(d_W1lo + k * H + n8);
    }

    CP_WAIT0();
    __syncthreads();
    convert_tile(smem, 0, 0, tid);
    if (blockIdx.x + grid < numTiles)
        issue_cp(x, sb, blockIdx.x + grid, 1, N, tid);
    __syncthreads();                     // abf[0] + B visible

    // hoisted fragment address components (relative)
    const uint32_t a_rel = (uint32_t)(warp_m * 16 + (lane & 15)) * RST_BF
                         + (uint32_t)((lane >> 4) * 8) * 2;
    const uint32_t b_off = sb + (uint32_t)(lane & 15) * RST_BF
                         + (uint32_t)(warp_n * 32 + (lane >> 4) * 8) * 2;

    int cur = 0, par = 0;
    for (long t = blockIdx.x; t < numTiles; t += grid, par ^= 1) {
        const long tn = t + grid, tnn = t + 2 * (long)grid;
        const bool hn = tn < numTiles, hnn = tnn < numTiles;

        // issue cp for t+2 into A32[cur] (its data was converted last iter)
        if (hnn) issue_cp(x, sb, tnn, cur, N, tid);
        // convert tile t+1 (A32[cur^1] -> abf[cur^1])
        if (hn) {
            if (hnn) { CP_WAIT1(); } else { CP_WAIT0(); }
            convert_tile(smem, cur ^ 1, cur ^ 1, tid);
        }

        // ---- MMA on abf[cur] ----
        float acc[4][4];
#pragma unroll
        for (int ni = 0; ni < 4; ni++)
#pragma unroll
            for (int r = 0; r < 4; r++) acc[ni][r] = 0.f;

        const uint32_t abfHi = sb + OFF_ABF + cur * ABF_BUF + a_rel;
        const uint32_t abfLo = abfHi + 17408;
#pragma unroll
        for (int k = 0; k < 8; k++) {
            uint32_t ah[4], al[4];
            ldsm_x4(ah, abfHi + k * 32);
            ldsm_x4(al, abfLo + k * 32);
#pragma unroll
            for (int nb = 0; nb < 2; nb++) {
                uint32_t bh[4], bl[4];
                uint32_t bo = b_off + (uint32_t)k * 16 * RST_BF + nb * 32;
                ldsm_x4_t(bh, bo + OFF_B_HI);
                ldsm_x4_t(bl, bo + OFF_B_LO);
                mma16816(acc[nb * 2],     ah, &bh[0]);
                mma16816(acc[nb * 2 + 1], ah, &bh[2]);
                mma16816(acc[nb * 2],     al, &bh[0]);
                mma16816(acc[nb * 2 + 1], al, &bh[2]);
                mma16816(acc[nb * 2],     ah, &bl[0]);
                mma16816(acc[nb * 2 + 1], ah, &bl[2]);
            }
        }

        // ---- epilogue: silu + dot(W2), warp row-reduce -> sgate[par] ----
        float* sgate = (float*)(smem + OFF_SGATE + par * 1024);
        float part[2] = {0.f, 0.f};
#pragma unroll
        for (int ni = 0; ni < 4; ni++)
#pragma unroll
            for (int r = 0; r < 4; r++) {
                int col = warp_n * 32 + ni * 8 + (lane & 3) * 2 + (r & 1);
                float vv = acc[ni][r] + sb1[col];
                float sl = vv / (1.f + __expf(-vv));
                part[r >> 1] = fmaf(sl, sw2[col], part[r >> 1]);
            }
#pragma unroll
        for (int hh = 0; hh < 2; hh++) {
            float p = part[hh];
            p += __shfl_xor_sync(0xFFFFFFFF, p, 1);
            p += __shfl_xor_sync(0xFFFFFFFF, p, 2);
            part[hh] = p;
        }
        if ((lane & 3) == 0) {
#pragma unroll
            for (int hh = 0; hh < 2; hh++) {
                int row = warp_m * 16 + hh * 8 + (lane >> 2);
                sgate[warp_n * 64 + row] = part[hh];
            }
        }
        __syncthreads();                 // abf[cur^1] + sgate[par] complete
        if (tid < 64) {
            long gm = t * 64 + tid;
            if (gm < N)
                d_gate[gm] = sgate[tid] + sgate[64 + tid]
                           + sgate[128 + tid] + sgate[192 + tid];
        }
        cur ^= 1;
    }
}

// ---------------------------------------------------------------------------
// Reduce kernel: per-segment mean/max/attention (b2 cancels in softmax)
// ---------------------------------------------------------------------------
__global__ __launch_bounds__(128) void reduce_kernel(
    const float* __restrict__ x, float* __restrict__ out)
{
    int b = blockIdx.x;
    int j = threadIdx.x;
    int s = d_seg_start[b];
    int e = (s < 0) ? 0 : d_seg_end[b];
    if (s < 0) s = 0;

    float sum = 0.f, mx = -CUDART_INF_F;
    float m0 = -CUDART_INF_F, dn0 = 0.f, ac0 = 0.f;
    float m1 = -CUDART_INF_F, dn1 = 0.f, ac1 = 0.f;

    int n = s;
    for (; n + 2 <= e; n += 2) {
        float xv0 = __ldg(x + (size_t)n * H + j);
        float g0  = d_gate[n];
        float xv1 = __ldg(x + (size_t)(n + 1) * H + j);
        float g1  = d_gate[n + 1];
        sum += xv0 + xv1;
        mx = fmaxf(mx, fmaxf(xv0, xv1));
        if (g0 > m0) { float sc = __expf(m0 - g0); dn0 *= sc; ac0 *= sc; m0 = g0; }
        float e0 = __expf(g0 - m0); dn0 += e0; ac0 = fmaf(e0, xv0, ac0);
        if (g1 > m1) { float sc = __expf(m1 - g1); dn1 *= sc; ac1 *= sc; m1 = g1; }
        float e1 = __expf(g1 - m1); dn1 += e1; ac1 = fmaf(e1, xv1, ac1);
    }
    if (n < e) {
        float xv = __ldg(x + (size_t)n * H + j);
        float g  = d_gate[n];
        sum += xv; mx = fmaxf(mx, xv);
        if (g > m0) { float sc = __expf(m0 - g); dn0 *= sc; ac0 *= sc; m0 = g; }
        float ev = __expf(g - m0); dn0 += ev; ac0 = fmaf(ev, xv, ac0);
    }

    int cnt = e - s;
    float denom = 0.f, acc = 0.f;
    if (cnt > 0) {
        float M  = fmaxf(m0, m1);
        float s0 = (m0 > -CUDART_INF_F) ? __expf(m0 - M) : 0.f;
        float s1 = (m1 > -CUDART_INF_F) ? __expf(m1 - M) : 0.f;
        denom = dn0 * s0 + dn1 * s1;
        acc   = ac0 * s0 + ac1 * s1;
    }
    float* o = out + (size_t)b * (3 * H);
    o[j]         = sum / fmaxf((float)cnt, 1.f);
    o[H + j]     = mx;
    o[2 * H + j] = (cnt > 0) ? (acc / denom) : 0.f;
}

// ---------------------------------------------------------------------------
extern "C" void kernel_launch(void* const* d_in, const int* in_sizes, int n_in,
                              void* d_out, int out_size) {
    const float* x  = (const float*)d_in[0];
    const float* W1 = (const float*)d_in[1];
    const float* b1 = (const float*)d_in[2];
    const float* W2 = (const float*)d_in[3];
    const int*   bi = (const int*)d_in[5];

    const int N = in_sizes[5];
    const int B = out_size / (3 * H);
    float* out = (float*)d_out;

    static int inited = 0;
    static int sms = 148;
    if (!inited) {
        cudaFuncSetAttribute(gate_mma_kernel,
                             cudaFuncAttributeMaxDynamicSharedMemorySize, SMEM_TOTAL);
        int dev = 0;
        cudaGetDevice(&dev);
        cudaDeviceGetAttribute(&sms, cudaDevAttrMultiProcessorCount, dev);
        inited = 1;
    }

    const int numTiles = (N + 63) / 64;
    const int gateGrid = sms < numTiles ? sms : numTiles;

    init_bounds_kernel<<<(B + 255) / 256, 256>>>(B);
    bounds_kernel<<<(N + 255) / 256, 256>>>(bi, N);
    prep_w1_kernel<<<(H * H + 255) / 256, 256>>>(W1);
    gate_mma_kernel<<<gateGrid, 512, SMEM_TOTAL>>>(x, b1, W2, N);
    reduce_kernel<<<B, H>>>(x, out);
}